// round 7
// baseline (speedup 1.0000x reference)
#include <cuda_runtime.h>

// Problem constants: N_UNIQUE=10000, N_BASES=10, FILTERS=16, B=32, L=100000
#define N_UNIQUE 10000
#define N_BASES  10
#define FILTERS  16
#define N_ELEMS  (32 * 100000)           // 3,200,000 elements, 16 floats each
#define TPB      256
// One warp handles a chunk of 32 elements: 3,200,000 / 32 = 100,000 chunks.
// 100,000 / 8 warps = 12,500 blocks exactly — no tail.
#define GATHER_BLOCKS (N_ELEMS / 32 / (TPB / 32))

// Precomputed bias-fused unique-value table, fp32 (device global scratch).
__device__ float g_tab[N_UNIQUE * FILTERS];   // row u = 16 floats = 64B

// Kernel 1: tab[u][f] = sum_b X_spline[u][b]*kernel[b][f] + bias[f]
__global__ void precompute_shrunk(const float* __restrict__ X_spline,
                                  const float* __restrict__ kern,
                                  const float* __restrict__ bias) {
    int t = blockIdx.x * blockDim.x + threadIdx.x;
    if (t >= N_UNIQUE * FILTERS) return;
    int u = t >> 4;
    int f = t & 15;
    float acc = __ldg(bias + f);
#pragma unroll
    for (int b = 0; b < N_BASES; ++b)
        acc = fmaf(__ldg(X_spline + u * N_BASES + b), __ldg(kern + b * FILTERS + f), acc);
    g_tab[t] = acc;
}

// Kernel 2: out[e][f] = tab[idx[e]][f].
// Warp chunk = 32 elements. Lane l owns float column (l&15).
// Every memory instruction touches exactly ONE 128B line:
//  - idx: 1x LDG.32 per chunk (32 lanes, 128B contiguous), shfl-broadcast
//  - gather: per element one LDG.32 with all 32 lanes inside that 64B row
//    (upper half duplicates lower = hardware broadcast, 1 wavefront)
//  - store: per element-pair one STG.32, 32 lanes x 4B = 128B contiguous
__global__ __launch_bounds__(TPB) void gather_out(const int* __restrict__ idx,
                                                  float* __restrict__ outf) {
    const unsigned warpId = blockIdx.x * (TPB / 32) + (threadIdx.x >> 5);
    const unsigned lane   = threadIdx.x & 31u;
    const unsigned eBase  = warpId * 32u;                 // first element of chunk

    // One idx load for the whole chunk (lane l holds idx[eBase+l]).
    const int u = __ldcs(idx + eBase + lane);

    const float* tabL   = g_tab + (lane & 15u);           // lane's column in any row
    float*       outPtr = outf + (size_t)eBase * 16u + lane;
    const bool   lower  = lane < 16u;

    // 16 pairs, processed in 2 batches of 8 for register-bounded MLP.
#pragma unroll
    for (int half = 0; half < 2; ++half) {
        float a[8], b[8];
#pragma unroll
        for (int q = 0; q < 8; ++q) {
            const int p  = half * 8 + q;
            const int uA = __shfl_sync(0xffffffffu, u, 2 * p);
            const int uB = __shfl_sync(0xffffffffu, u, 2 * p + 1);
            a[q] = __ldg(tabL + (unsigned)uA * 16u);      // 1 line (broadcast)
            b[q] = __ldg(tabL + (unsigned)uB * 16u);      // 1 line (broadcast)
        }
#pragma unroll
        for (int q = 0; q < 8; ++q) {
            const int p = half * 8 + q;
            __stcs(outPtr + p * 32, lower ? a[q] : b[q]); // 128B contiguous
        }
    }
}

extern "C" void kernel_launch(void* const* d_in, const int* in_sizes, int n_in,
                              void* d_out, int out_size) {
    // Identify inputs by element count (all distinct):
    // idx: 3,200,000 | X_spline: 100,000 | kernel: 160 | bias: 16
    const int*   idx      = nullptr;
    const float* X_spline = nullptr;
    const float* kern     = nullptr;
    const float* bias     = nullptr;
    for (int i = 0; i < n_in; ++i) {
        switch (in_sizes[i]) {
            case N_ELEMS:             idx      = (const int*)  d_in[i]; break;
            case N_UNIQUE * N_BASES:  X_spline = (const float*)d_in[i]; break;
            case N_BASES * FILTERS:   kern     = (const float*)d_in[i]; break;
            case FILTERS:             bias     = (const float*)d_in[i]; break;
            default: break;
        }
    }

    {
        int total = N_UNIQUE * FILTERS;
        precompute_shrunk<<<(total + TPB - 1) / TPB, TPB>>>(X_spline, kern, bias);
    }
    gather_out<<<GATHER_BLOCKS, TPB>>>(idx, (float*)d_out);
}